// round 1
// baseline (speedup 1.0000x reference)
#include <cuda_runtime.h>

#define BB 32
#define NN 65536
#define BPB 32            // blocks per batch
#define THREADS 256
#define CHUNK 8           // points per thread: BPB*THREADS*CHUNK == NN
#define NACC 27           // 21 upper-tri H + 6 g

// Scratch: per-point [t0..t5, s, pad] (t = a*invd, s = g_d*invd), 8 floats for
// float4-aligned access. 32*65536*8 floats = 64 MB.
__device__ float g_scratch[(size_t)BB * NN * 8];
// Per-block partial reductions (overwritten every call -> no zeroing needed).
__device__ float g_part[BB * BPB * NACC];

__global__ void __launch_bounds__(THREADS)
pass1_kernel(const float* __restrict__ r, const float* __restrict__ w,
             const float* __restrict__ Jp, const float* __restrict__ Jd,
             const float* __restrict__ lm)
{
    const int b   = blockIdx.x / BPB;
    const int blk = blockIdx.x % BPB;
    const float lmbda = __ldg(lm);

    float acc[NACC];
#pragma unroll
    for (int i = 0; i < NACC; i++) acc[i] = 0.0f;

    const int base_pt = b * NN + blk * (THREADS * CHUNK);

    const float2* __restrict__ r2  = (const float2*)r;
    const float2* __restrict__ w2  = (const float2*)w;
    const float2* __restrict__ jd2 = (const float2*)Jd;
    const float4* __restrict__ jp4 = (const float4*)Jp;
    float4* __restrict__ scr = (float4*)g_scratch;

#pragma unroll 2
    for (int c = 0; c < CHUNK; c++) {
        const int p = base_pt + c * THREADS + threadIdx.x;

        // J_p: 12 contiguous floats per point, [k=0][i=0..5], [k=1][i=0..5]
        float4 A = jp4[p * 3 + 0];
        float4 Bv = jp4[p * 3 + 1];
        float4 C = jp4[p * 3 + 2];
        float jp[12] = {A.x, A.y, A.z, A.w, Bv.x, Bv.y, Bv.z, Bv.w,
                        C.x, C.y, C.z, C.w};
        float2 wv = w2[p];
        float2 rv = r2[p];
        float2 jd = jd2[p];

        const float u0 = wv.x * jd.x;          // w*J_d per k
        const float u1 = wv.y * jd.y;
        const float d  = jd.x * u0 + jd.y * u1; // H_dd core
        const float gd = rv.x * u0 + rv.y * u1; // g_d
        const float invd = 1.0f / (d + lmbda + 1e-8f);

        float a[6], t[6], x0[6], x1[6];
#pragma unroll
        for (int i = 0; i < 6; i++) {
            a[i] = jp[i] * u0 + jp[6 + i] * u1;   // H_pd row
            t[i] = a[i] * invd;
            x0[i] = wv.x * jp[i];
            x1[i] = wv.y * jp[6 + i];
        }
        const float s = gd * invd;

        // scratch for pass 2
        scr[p * 2 + 0] = make_float4(t[0], t[1], t[2], t[3]);
        scr[p * 2 + 1] = make_float4(t[4], t[5], s, 0.0f);

        // H_eff upper triangle (S - Schur) and g_eff
        int idx = 0;
#pragma unroll
        for (int i = 0; i < 6; i++) {
#pragma unroll
            for (int j = i; j < 6; j++) {
                acc[idx] += x0[i] * jp[j] + x1[i] * jp[6 + j] - a[i] * t[j];
                idx++;
            }
            acc[21 + i] += x0[i] * rv.x + x1[i] * rv.y - t[i] * gd;
        }
    }

    // Block reduction: warp shuffle, then cross-warp via shared.
    __shared__ float sh[NACC][THREADS / 32];
    const int lane = threadIdx.x & 31;
    const int warp = threadIdx.x >> 5;
#pragma unroll
    for (int i = 0; i < NACC; i++) {
        float v = acc[i];
#pragma unroll
        for (int off = 16; off > 0; off >>= 1)
            v += __shfl_xor_sync(0xFFFFFFFFu, v, off);
        if (lane == 0) sh[i][warp] = v;
    }
    __syncthreads();
    if (threadIdx.x < NACC) {
        float v = 0.0f;
#pragma unroll
        for (int k = 0; k < THREADS / 32; k++) v += sh[threadIdx.x][k];
        g_part[(size_t)blockIdx.x * NACC + threadIdx.x] = v;
    }
}

// One block per batch: reduce BPB partials, solve 6x6, write delta_pose.
__global__ void solve_kernel(float* __restrict__ out, const float* __restrict__ lm)
{
    const int b = blockIdx.x;
    __shared__ float H[NACC];
    if (threadIdx.x < NACC) {
        float v = 0.0f;
        for (int k = 0; k < BPB; k++)
            v += g_part[(size_t)(b * BPB + k) * NACC + threadIdx.x];
        H[threadIdx.x] = v;
    }
    __syncthreads();

    if (threadIdx.x == 0) {
        const float lmbda = __ldg(lm);
        float M[6][7];
        int idx = 0;
        for (int i = 0; i < 6; i++)
            for (int j = i; j < 6; j++) {
                float v = H[idx++];
                M[i][j] = v;
                M[j][i] = v;
            }
        for (int i = 0; i < 6; i++) {
            M[i][i] += lmbda + 1e-4f;   // +lmbda*I (H_pp) and +eps*I
            M[i][6] = H[21 + i];        // g_eff
        }
        // Gauss-Jordan (SPD -> no pivoting needed)
#pragma unroll
        for (int k = 0; k < 6; k++) {
            float inv = 1.0f / M[k][k];
#pragma unroll
            for (int j = 0; j < 7; j++) M[k][j] *= inv;
#pragma unroll
            for (int i = 0; i < 6; i++) {
                if (i == k) continue;
                float f = M[i][k];
#pragma unroll
                for (int j = 0; j < 7; j++) M[i][j] -= f * M[k][j];
            }
        }
#pragma unroll
        for (int i = 0; i < 6; i++) out[b * 6 + i] = M[i][6];
    }
}

// Back-substitute depths: delta_depth = s - t . dp
__global__ void __launch_bounds__(THREADS)
pass2_kernel(float* __restrict__ out)
{
    const int b   = blockIdx.x / BPB;
    const int blk = blockIdx.x % BPB;

    __shared__ float dp[6];
    if (threadIdx.x < 6) dp[threadIdx.x] = out[b * 6 + threadIdx.x];
    __syncthreads();

    const float d0 = dp[0], d1 = dp[1], d2 = dp[2];
    const float d3 = dp[3], d4 = dp[4], d5 = dp[5];

    const int base_pt = b * NN + blk * (THREADS * CHUNK);
    const float4* __restrict__ scr = (const float4*)g_scratch;
    float* __restrict__ dd = out + BB * 6;

#pragma unroll 2
    for (int c = 0; c < CHUNK; c++) {
        const int p = base_pt + c * THREADS + threadIdx.x;
        float4 s0 = scr[p * 2 + 0];
        float4 s1 = scr[p * 2 + 1];
        float v = s1.z - (s0.x * d0 + s0.y * d1 + s0.z * d2 +
                          s0.w * d3 + s1.x * d4 + s1.y * d5);
        dd[p] = v;
    }
}

extern "C" void kernel_launch(void* const* d_in, const int* in_sizes, int n_in,
                              void* d_out, int out_size)
{
    const float* r  = (const float*)d_in[0];
    const float* w  = (const float*)d_in[1];
    const float* Jp = (const float*)d_in[2];
    const float* Jd = (const float*)d_in[3];
    const float* lm = (const float*)d_in[4];
    float* out = (float*)d_out;

    pass1_kernel<<<BB * BPB, THREADS>>>(r, w, Jp, Jd, lm);
    solve_kernel<<<BB, 32>>>(out, lm);
    pass2_kernel<<<BB * BPB, THREADS>>>(out);
}

// round 4
// speedup vs baseline: 1.0903x; 1.0903x over previous
// R3: identical to R2 candidate — two prior runs died at container acquire
// (broker infra), so this is the first real measurement of this design.
#include <cuda_runtime.h>
#include <math.h>

#define BB 32
#define NN 65536
#define BPB 16            // segments per batch
#define THREADS 256
#define CHUNK 16          // points per thread: BPB*THREADS*CHUNK == NN
#define NSEG (BB * BPB)   // 512 blocks = ~one full wave at 4 CTAs/SM
#define NACC 27           // 21 upper-tri H + 6 g

// Scratch for pass 2: t0..t3 | t4,t5 | s   (t = a*invd, s = g_d*invd). 56 MB.
__device__ float4 g_scrA[(size_t)BB * NN];
__device__ float2 g_scrB[(size_t)BB * NN];
__device__ float  g_scrC[(size_t)BB * NN];
// Per-segment partial reductions (overwritten every call -> no zeroing needed).
__device__ float g_part[NSEG * NACC];

__global__ void __launch_bounds__(THREADS, 4)
pass1_kernel(const float* __restrict__ r, const float* __restrict__ w,
             const float* __restrict__ Jp, const float* __restrict__ Jd,
             const float* __restrict__ lm)
{
    const int b   = blockIdx.x / BPB;
    const int blk = blockIdx.x % BPB;
    const float lmbda = __ldg(lm);

    float acc[NACC];
#pragma unroll
    for (int i = 0; i < NACC; i++) acc[i] = 0.0f;

    const int base_pt = b * NN + blk * (THREADS * CHUNK);

    const float2* __restrict__ r2  = (const float2*)r;
    const float2* __restrict__ w2  = (const float2*)w;
    const float2* __restrict__ jd2 = (const float2*)Jd;
    const float4* __restrict__ jp4 = (const float4*)Jp;

#pragma unroll 2
    for (int c = 0; c < CHUNK; c++) {
        const int p = base_pt + c * THREADS + threadIdx.x;

        // Streaming loads (evict-first) so scratch stores stay resident in L2.
        const float4 A  = __ldcs(&jp4[p * 3 + 0]);
        const float4 Bv = __ldcs(&jp4[p * 3 + 1]);
        const float4 C  = __ldcs(&jp4[p * 3 + 2]);
        const float2 wv = __ldcs(&w2[p]);
        const float2 rv = __ldcs(&r2[p]);
        const float2 jd = __ldcs(&jd2[p]);

        const float sw0 = sqrtf(wv.x);
        const float sw1 = sqrtf(wv.y);
        // y = sqrt(w)*J_p ; primes = sqrt(w)*{J_d, r}
        const float jp0[6] = {A.x, A.y, A.z, A.w, Bv.x, Bv.y};
        const float jp1[6] = {Bv.z, Bv.w, C.x, C.y, C.z, C.w};

        const float jd0 = sw0 * jd.x;
        const float jd1 = sw1 * jd.y;
        const float rr0 = sw0 * rv.x;
        const float rr1 = sw1 * rv.y;

        const float d  = jd0 * jd0 + jd1 * jd1;   // H_dd core
        const float gd = rr0 * jd0 + rr1 * jd1;   // g_d
        const float invd = 1.0f / (d + lmbda + 1e-8f);
        const float s = gd * invd;

        float y0[6], y1[6], a[6], t[6];
#pragma unroll
        for (int i = 0; i < 6; i++) {
            y0[i] = sw0 * jp0[i];
            y1[i] = sw1 * jp1[i];
            a[i]  = y0[i] * jd0 + y1[i] * jd1;    // H_pd row
            t[i]  = a[i] * invd;
        }

        // scratch for pass 2
        g_scrA[p] = make_float4(t[0], t[1], t[2], t[3]);
        g_scrB[p] = make_float2(t[4], t[5]);
        g_scrC[p] = s;

        // H_eff upper triangle (H_pp - Schur) and g_eff
        int idx = 0;
#pragma unroll
        for (int i = 0; i < 6; i++) {
#pragma unroll
            for (int j = i; j < 6; j++) {
                acc[idx] += y0[i] * y0[j] + y1[i] * y1[j] - a[i] * t[j];
                idx++;
            }
            acc[21 + i] += y0[i] * rr0 + y1[i] * rr1 - t[i] * gd;
        }
    }

    // Block reduction: warp shuffle, then cross-warp via shared.
    __shared__ float sh[NACC][THREADS / 32];
    const int lane = threadIdx.x & 31;
    const int warp = threadIdx.x >> 5;
#pragma unroll
    for (int i = 0; i < NACC; i++) {
        float v = acc[i];
#pragma unroll
        for (int off = 16; off > 0; off >>= 1)
            v += __shfl_xor_sync(0xFFFFFFFFu, v, off);
        if (lane == 0) sh[i][warp] = v;
    }
    __syncthreads();
    if (threadIdx.x < NACC) {
        float v = 0.0f;
#pragma unroll
        for (int k = 0; k < THREADS / 32; k++) v += sh[threadIdx.x][k];
        g_part[(size_t)blockIdx.x * NACC + threadIdx.x] = v;
    }
}

// Fused: reduce partials + 6x6 solve (redundant per block, cheap) + depth
// back-substitution. delta_depth = s - t . dp
__global__ void __launch_bounds__(THREADS)
pass2_kernel(float* __restrict__ out, const float* __restrict__ lm)
{
    const int b   = blockIdx.x / BPB;
    const int blk = blockIdx.x % BPB;

    __shared__ float H[NACC];
    __shared__ float dp[6];

    if (threadIdx.x < NACC) {
        float v = 0.0f;
#pragma unroll
        for (int k = 0; k < BPB; k++)
            v += g_part[(size_t)(b * BPB + k) * NACC + threadIdx.x];
        H[threadIdx.x] = v;
    }
    __syncthreads();

    if (threadIdx.x == 0) {
        const float lmbda = __ldg(lm);
        float M[6][7];
        int idx = 0;
#pragma unroll
        for (int i = 0; i < 6; i++)
#pragma unroll
            for (int j = i; j < 6; j++) {
                float v = H[idx++];
                M[i][j] = v;
                M[j][i] = v;
            }
#pragma unroll
        for (int i = 0; i < 6; i++) {
            M[i][i] += lmbda + 1e-4f;   // +lmbda*I (H_pp) and +eps*I
            M[i][6] = H[21 + i];        // g_eff
        }
        // Gauss-Jordan (SPD -> no pivoting needed)
#pragma unroll
        for (int k = 0; k < 6; k++) {
            float inv = 1.0f / M[k][k];
#pragma unroll
            for (int j = 0; j < 7; j++) M[k][j] *= inv;
#pragma unroll
            for (int i = 0; i < 6; i++) {
                if (i == k) continue;
                float f = M[i][k];
#pragma unroll
                for (int j = 0; j < 7; j++) M[i][j] -= f * M[k][j];
            }
        }
#pragma unroll
        for (int i = 0; i < 6; i++) dp[i] = M[i][6];
        if (blk == 0) {
#pragma unroll
            for (int i = 0; i < 6; i++) out[b * 6 + i] = dp[i];
        }
    }
    __syncthreads();

    const float d0 = dp[0], d1 = dp[1], d2 = dp[2];
    const float d3 = dp[3], d4 = dp[4], d5 = dp[5];

    const int base_pt = b * NN + blk * (THREADS * CHUNK);
    float* __restrict__ dd = out + BB * 6;

#pragma unroll 2
    for (int c = 0; c < CHUNK; c++) {
        const int p = base_pt + c * THREADS + threadIdx.x;
        const float4 s0 = __ldcs(&g_scrA[p]);
        const float2 s1 = __ldcs(&g_scrB[p]);
        const float  s  = __ldcs(&g_scrC[p]);
        dd[p] = s - (s0.x * d0 + s0.y * d1 + s0.z * d2 +
                     s0.w * d3 + s1.x * d4 + s1.y * d5);
    }
}

extern "C" void kernel_launch(void* const* d_in, const int* in_sizes, int n_in,
                              void* d_out, int out_size)
{
    const float* r  = (const float*)d_in[0];
    const float* w  = (const float*)d_in[1];
    const float* Jp = (const float*)d_in[2];
    const float* Jd = (const float*)d_in[3];
    const float* lm = (const float*)d_in[4];
    float* out = (float*)d_out;

    pass1_kernel<<<NSEG, THREADS>>>(r, w, Jp, Jd, lm);
    pass2_kernel<<<NSEG, THREADS>>>(out, lm);
}